// round 13
// baseline (speedup 1.0000x reference)
#include <cuda_runtime.h>
#include <cstdint>

// Problem constants (fixed by setup_inputs)
#define B_   16
#define T_   8192
#define C_   256
#define STRIDE_ 64
#define NCHUNK_ 126          // (T_ - W0_) / STRIDE_
#define W0_  128
#define W1_  64
#define W2_  16

// Output offsets (float elements), leaf order: K0,V0,K1,V1,K2,V2,recon
#define K0_OFF  0
#define V0_OFF  (B_*W0_*C_)                    // 524288
#define K1_OFF  (V0_OFF + B_*W0_*C_)           // 1048576
#define V1_OFF  (K1_OFF + B_*W1_*C_)           // 1310720
#define K2_OFF  (V1_OFF + B_*W1_*C_)           // 1572864
#define V2_OFF  (K2_OFF + B_*W2_*C_)           // 1638400
#define RECON_OFF (V2_OFF + B_*W2_*C_)         // 1703936

#define NBLK1 (B_*NCHUNK_)   // 2016 pooling blocks
#define NCOPYBLK 128         // 128 blocks * 256 thr * 4 float4 = 131072 = B_*W0_*C_/4
#define NPAIR (B_*32)        // 512 level-2 pairs
#define NBLK2 (NPAIR/8)      // 64 blocks, 8 warps = 8 pairs per block

__device__ float g_part1[NBLK1];
__device__ float g_part2[NPAIR];
__device__ unsigned int g_done2 = 0;   // level-2 completion counter (self-resetting)

__device__ __forceinline__ float dot4(float4 a, float4 b) {
    return fmaf(a.x, b.x, fmaf(a.y, b.y, fmaf(a.z, b.z, a.w * b.w)));
}

// ---------------------------------------------------------------------------
// Kernel 1: K0/V0 copy (blocks [0, NCOPYBLK)) + level-1 pooling (blocks
// [NCOPYBLK, NCOPYBLK+NBLK1)). 256 threads.
// Dynamic smem: Ks[64*256] + q0s[256] + w[64] + red[32] = 66,944 B -> 3 CTA/SM
// ---------------------------------------------------------------------------
__global__ __launch_bounds__(256) void level1_kernel(
        const float* __restrict__ K, const float* __restrict__ V,
        const float* __restrict__ q0, float* __restrict__ out) {
    const int tid  = threadIdx.x;

    // ---- Copy blocks first: K0 = K[:, T-128:], V0 = V[:, T-128:] --------
    if (blockIdx.x < NCOPYBLK) {
        const float4* K4 = reinterpret_cast<const float4*>(K);
        const float4* V4 = reinterpret_cast<const float4*>(V);
        float4* out4 = reinterpret_cast<float4*>(out);
        const int C4 = C_ / 4;                 // 64
        const int per_b = W0_ * C4;            // 8192 float4 per batch tile
        const int blk_base = blockIdx.x * 1024;
        const int b = blk_base / per_b;
        const size_t src_base =
            ((size_t)b * T_ + (T_ - W0_)) * C4 + (blk_base % per_b);
        float4 kv[4], vv[4];
        #pragma unroll
        for (int j = 0; j < 4; j++) kv[j] = __ldcs(&K4[src_base + j * 256 + tid]);
        #pragma unroll
        for (int j = 0; j < 4; j++) vv[j] = __ldcs(&V4[src_base + j * 256 + tid]);
        #pragma unroll
        for (int j = 0; j < 4; j++) {
            int i = blk_base + j * 256 + tid;
            __stcs(&out4[K0_OFF / 4 + i], kv[j]);
            __stcs(&out4[V0_OFF / 4 + i], vv[j]);
        }
        return;
    }

    // ---- Pooling blocks -------------------------------------------------
    extern __shared__ float sm[];
    float* Ks  = sm;                 // 64*256
    float* q0s = Ks + 64 * C_;       // 256
    float* wsh = q0s + C_;           // 64 (raw logits)
    float* red = wsh + 64;           // 32

    const int lane = tid & 31;
    const int wid  = tid >> 5;

    const int pb = blockIdx.x - NCOPYBLK;     // 0 .. NBLK1-1
    const int b = pb / NCHUNK_;
    const int n = pb % NCHUNK_;
    const size_t base = ((size_t)b * T_ + (size_t)n * STRIDE_) * C_;

    // Stage K chunk into smem (float4, evict-first: single DRAM touch)
    {
        const float4* Kg  = reinterpret_cast<const float4*>(K + base);
        float4*       Ks4 = reinterpret_cast<float4*>(Ks);
        #pragma unroll
        for (int i = 0; i < 16; i++)
            Ks4[i * 256 + tid] = __ldcs(&Kg[i * 256 + tid]);
        q0s[tid] = q0[tid];
    }
    __syncthreads();

    // Logits: warp wid handles rows s = wid*8 .. wid*8+7 (conflict-free LDS)
    {
        float qv[8];
        #pragma unroll
        for (int i = 0; i < 8; i++) qv[i] = q0s[lane + 32 * i];
        #pragma unroll
        for (int r = 0; r < 8; r++) {
            int s = wid * 8 + r;
            const float* row = Ks + s * C_;
            float acc = 0.f;
            #pragma unroll
            for (int i = 0; i < 8; i++) acc = fmaf(row[lane + 32 * i], qv[i], acc);
            #pragma unroll
            for (int off = 16; off; off >>= 1)
                acc += __shfl_xor_sync(0xffffffffu, acc, off);
            if (lane == 0) wsh[s] = acc;
        }
    }
    __syncthreads();

    // Softmax computed REDUNDANTLY by every warp (identical values) — no
    // warp0-only phase, no extra barrier. Weights kept in 2 regs per lane:
    // lane l holds w[l] (wlo) and w[l+32] (whi); consumers shuffle.
    float wlo, whi;
    {
        float l0 = wsh[lane], l1 = wsh[lane + 32];
        float m = fmaxf(l0, l1);
        #pragma unroll
        for (int off = 16; off; off >>= 1)
            m = fmaxf(m, __shfl_xor_sync(0xffffffffu, m, off));
        float e0 = __expf(l0 - m), e1 = __expf(l1 - m);
        float ssum = e0 + e1;
        #pragma unroll
        for (int off = 16; off; off >>= 1)
            ssum += __shfl_xor_sync(0xffffffffu, ssum, off);
        float inv = 1.f / ssum;
        wlo = e0 * inv;
        whi = e1 * inv;
    }

    // Per-column (thread = column c) merged pass:
    //   sk, sum(x), sum(x^2) from smem K; sv streamed from global V.
    const int c = tid;
    const float* Vg = V + base;
    float sk = 0.f, sx = 0.f, sxx = 0.f, sv = 0.f;
    #pragma unroll 8
    for (int s = 0; s < 64; s++) {
        float w = __shfl_sync(0xffffffffu, (s < 32) ? wlo : whi, s & 31);
        float v = __ldcs(&Vg[s * C_ + c]);   // single-use stream, evict-first
        float x = Ks[s * C_ + c];
        sk  = fmaf(w, x, sk);
        sx += x;
        sxx = fmaf(x, x, sxx);
        sv  = fmaf(w, v, sv);
    }
    // sum_s (x - sk)^2 = sxx - 2*sk*sx + 64*sk^2
    float rp = sxx - 2.f * sk * sx + 64.f * sk * sk;

    // Outputs: only last W1_ chunks feed K1/V1
    if (n >= NCHUNK_ - W1_) {
        int j = n - (NCHUNK_ - W1_);
        size_t o = ((size_t)b * W1_ + j) * C_ + c;
        out[K1_OFF + o] = sk;
        out[V1_OFF + o] = sv;
    }

    // Block-reduce rp -> g_part1 (deterministic: fixed tree, fixed mapping)
    #pragma unroll
    for (int off = 16; off; off >>= 1)
        rp += __shfl_xor_sync(0xffffffffu, rp, off);
    if (lane == 0) red[wid] = rp;
    __syncthreads();
    if (wid == 0) {
        float v = (lane < 8) ? red[lane] : 0.f;
        #pragma unroll
        for (int off = 4; off; off >>= 1)
            v += __shfl_xor_sync(0xffffffffu, v, off);
        if (lane == 0)
            // rl[n] = sum/(B*stride*C); recon1 = sum_n rl[n] / NCHUNK
            g_part1[pb] = v * (1.0f / ((float)(B_ * STRIDE_ * C_) * (float)NCHUNK_));
    }
}

// ---------------------------------------------------------------------------
// Kernel 2: one WARP per pair; no block barriers in main path.
// Block = 256 thr = 8 warps = 8 pairs; grid = 64 blocks.
// Lane l owns columns [4l,4l+4) and [128+4l,128+4l+4) as two float4s per row.
// The LAST block (counter election) does the deterministic recon reduction.
// ---------------------------------------------------------------------------
__global__ __launch_bounds__(256) void level2_kernel(
        const float* __restrict__ out_in, const float* __restrict__ q1,
        float* __restrict__ out) {
    __shared__ unsigned int s_last;
    __shared__ float redf[8];

    const int tid  = threadIdx.x;
    const int lane = tid & 31;
    const int wid  = tid >> 5;
    const int gp = blockIdx.x * 8 + wid;      // global pair 0..511
    const int b = gp >> 5;
    const int p = gp & 31;

    const float4* K1 = reinterpret_cast<const float4*>(out_in + K1_OFF);
    const float4* V1 = reinterpret_cast<const float4*>(out_in + V1_OFF);
    const float4* q4 = reinterpret_cast<const float4*>(q1);
    const int C4 = C_ / 4;                    // 64 float4 per row

    const size_t r0 = ((size_t)b * W1_ + 2 * p) * C4;   // float4 units
    // 8 independent loads per source row pair — batched MLP
    float4 k0a = K1[r0 + lane],       k0b = K1[r0 + 32 + lane];
    float4 k1a = K1[r0 + C4 + lane],  k1b = K1[r0 + C4 + 32 + lane];
    float4 v0a = V1[r0 + lane],       v0b = V1[r0 + 32 + lane];
    float4 v1a = V1[r0 + C4 + lane],  v1b = V1[r0 + C4 + 32 + lane];
    float4 qa  = q4[lane],            qb  = q4[32 + lane];

    // Logits via pure warp shuffles (no smem, no barrier)
    float d0 = dot4(k0a, qa) + dot4(k0b, qb);
    float d1 = dot4(k1a, qa) + dot4(k1b, qb);
    #pragma unroll
    for (int off = 16; off; off >>= 1) {
        d0 += __shfl_xor_sync(0xffffffffu, d0, off);
        d1 += __shfl_xor_sync(0xffffffffu, d1, off);
    }
    // all lanes now hold full sums; softmax in registers
    float m = fmaxf(d0, d1);
    float e0 = __expf(d0 - m), e1 = __expf(d1 - m);
    float inv = 1.f / (e0 + e1);
    float w0 = e0 * inv, w1 = e1 * inv;

    float4 ska, skb, sva, svb;
    ska.x = w0*k0a.x + w1*k1a.x; ska.y = w0*k0a.y + w1*k1a.y;
    ska.z = w0*k0a.z + w1*k1a.z; ska.w = w0*k0a.w + w1*k1a.w;
    skb.x = w0*k0b.x + w1*k1b.x; skb.y = w0*k0b.y + w1*k1b.y;
    skb.z = w0*k0b.z + w1*k1b.z; skb.w = w0*k0b.w + w1*k1b.w;
    sva.x = w0*v0a.x + w1*v1a.x; sva.y = w0*v0a.y + w1*v1a.y;
    sva.z = w0*v0a.z + w1*v1a.z; sva.w = w0*v0a.w + w1*v1a.w;
    svb.x = w0*v0b.x + w1*v1b.x; svb.y = w0*v0b.y + w1*v1b.y;
    svb.z = w0*v0b.z + w1*v1b.z; svb.w = w0*v0b.w + w1*v1b.w;

    // Outputs: last W2_ pairs
    if (p >= 32 - W2_) {
        int j = p - (32 - W2_);
        size_t o = ((size_t)b * W2_ + j) * C4;
        float4* out4 = reinterpret_cast<float4*>(out);
        out4[K2_OFF / 4 + o + lane]      = ska;
        out4[K2_OFF / 4 + o + 32 + lane] = skb;
        out4[V2_OFF / 4 + o + lane]      = sva;
        out4[V2_OFF / 4 + o + 32 + lane] = svb;
    }

    // rl2 partial: sum over this pair's 2*C elements of (k - sk)^2
    float rp = 0.f;
    {
        float t;
        t = k0a.x-ska.x; rp = fmaf(t,t,rp);  t = k1a.x-ska.x; rp = fmaf(t,t,rp);
        t = k0a.y-ska.y; rp = fmaf(t,t,rp);  t = k1a.y-ska.y; rp = fmaf(t,t,rp);
        t = k0a.z-ska.z; rp = fmaf(t,t,rp);  t = k1a.z-ska.z; rp = fmaf(t,t,rp);
        t = k0a.w-ska.w; rp = fmaf(t,t,rp);  t = k1a.w-ska.w; rp = fmaf(t,t,rp);
        t = k0b.x-skb.x; rp = fmaf(t,t,rp);  t = k1b.x-skb.x; rp = fmaf(t,t,rp);
        t = k0b.y-skb.y; rp = fmaf(t,t,rp);  t = k1b.y-skb.y; rp = fmaf(t,t,rp);
        t = k0b.z-skb.z; rp = fmaf(t,t,rp);  t = k1b.z-skb.z; rp = fmaf(t,t,rp);
        t = k0b.w-skb.w; rp = fmaf(t,t,rp);  t = k1b.w-skb.w; rp = fmaf(t,t,rp);
    }
    #pragma unroll
    for (int off = 16; off; off >>= 1)
        rp += __shfl_xor_sync(0xffffffffu, rp, off);
    if (lane == 0)
        // rl2[p] = sum/(B*2*C); recon2 = 0.5 * sum_p rl2[p]
        g_part2[gp] = 0.5f * rp * (1.0f / (float)(B_ * 2 * C_));

    // ---- Last-block-done recon reduction --------------------------------
    __syncthreads();                           // all 8 warps' partials written
    if (tid == 0) {
        __threadfence();                       // make g_part2 writes visible
        unsigned int t = atomicAdd(&g_done2, 1u);
        s_last = (t == NBLK2 - 1) ? 1u : 0u;
    }
    __syncthreads();
    if (s_last) {
        __threadfence();                       // acquire all blocks' partials
        float a = 0.f;
        // Fixed index order + fixed thread mapping => deterministic sum
        for (int i = tid; i < NBLK1; i += 256) a += g_part1[i];
        for (int i = tid; i < NPAIR; i += 256) a += g_part2[i];
        #pragma unroll
        for (int off = 16; off; off >>= 1)
            a += __shfl_xor_sync(0xffffffffu, a, off);
        if (lane == 0) redf[wid] = a;
        __syncthreads();
        if (tid == 0) {
            float v = 0.f;
            #pragma unroll
            for (int i = 0; i < 8; i++) v += redf[i];
            out[RECON_OFF] = v;
            g_done2 = 0;                       // reset for next graph replay
        }
    }
}

// ---------------------------------------------------------------------------
extern "C" void kernel_launch(void* const* d_in, const int* in_sizes, int n_in,
                              void* d_out, int out_size) {
    const float* K  = (const float*)d_in[0];
    const float* V  = (const float*)d_in[1];
    const float* q0 = (const float*)d_in[2];
    const float* q1 = (const float*)d_in[3];
    float* out = (float*)d_out;

    // smem for level1: (64*256 + 256 + 64 + 32) floats = 66,944 bytes
    const int smem1 = (64 * C_ + C_ + 64 + 32) * sizeof(float);
    cudaFuncSetAttribute(level1_kernel,
                         cudaFuncAttributeMaxDynamicSharedMemorySize, smem1);

    // K0/V0 copy (front blocks) + level-1 pooling in one grid
    level1_kernel<<<NCOPYBLK + NBLK1, 256, smem1>>>(K, V, q0, out);
    // Level 2: warp-per-pair + fused deterministic recon reduction
    level2_kernel<<<NBLK2, 256>>>(out, q1, out);
}

// round 16
// speedup vs baseline: 1.1101x; 1.1101x over previous
#include <cuda_runtime.h>
#include <cstdint>

// Problem constants (fixed by setup_inputs)
#define B_   16
#define T_   8192
#define C_   256
#define STRIDE_ 64
#define NCHUNK_ 126          // (T_ - W0_) / STRIDE_
#define W0_  128
#define W1_  64
#define W2_  16

// Output offsets (float elements), leaf order: K0,V0,K1,V1,K2,V2,recon
#define K0_OFF  0
#define V0_OFF  (B_*W0_*C_)                    // 524288
#define K1_OFF  (V0_OFF + B_*W0_*C_)           // 1048576
#define V1_OFF  (K1_OFF + B_*W1_*C_)           // 1310720
#define K2_OFF  (V1_OFF + B_*W1_*C_)           // 1572864
#define V2_OFF  (K2_OFF + B_*W2_*C_)           // 1638400
#define RECON_OFF (V2_OFF + B_*W2_*C_)         // 1703936

#define NBLK1 (B_*NCHUNK_)   // 2016 pooling blocks
#define NCOPYBLK 128         // 128 blocks * 256 thr * 4 float4 = 131072 = B_*W0_*C_/4
#define NPAIR (B_*32)        // 512 level-2 pairs
#define NBLK2 (NPAIR/8)      // 64 blocks, 8 warps = 8 pairs per block

__device__ float g_part1[NBLK1];
__device__ float g_part2[NPAIR];
__device__ unsigned int g_done2 = 0;   // level-2 completion counter (self-resetting)

__device__ __forceinline__ float dot4(float4 a, float4 b) {
    return fmaf(a.x, b.x, fmaf(a.y, b.y, fmaf(a.z, b.z, a.w * b.w)));
}

// ---------------------------------------------------------------------------
// Kernel 1 (measured-72.2us form): K0/V0 copy + level-1 pooling.
// Warp0-only softmax -> wsh holds normalized weights; merged loop reads
// wsh[s] as a conflict-free LDS broadcast (cheaper than SHFL in the hot loop
// — the R12 shuffle broadcast cost +8us, measured).
// Dynamic smem: Ks[64*256] + q0s[256] + w[64] + red[32] = 66,944 B -> 3 CTA/SM
// ---------------------------------------------------------------------------
__global__ __launch_bounds__(256) void level1_kernel(
        const float* __restrict__ K, const float* __restrict__ V,
        const float* __restrict__ q0, float* __restrict__ out) {
    const int tid  = threadIdx.x;

    // ---- Copy blocks first: K0 = K[:, T-128:], V0 = V[:, T-128:] --------
    if (blockIdx.x < NCOPYBLK) {
        const float4* K4 = reinterpret_cast<const float4*>(K);
        const float4* V4 = reinterpret_cast<const float4*>(V);
        float4* out4 = reinterpret_cast<float4*>(out);
        const int C4 = C_ / 4;                 // 64
        const int per_b = W0_ * C4;            // 8192 float4 per batch tile
        const int blk_base = blockIdx.x * 1024;
        const int b = blk_base / per_b;
        const size_t src_base =
            ((size_t)b * T_ + (T_ - W0_)) * C4 + (blk_base % per_b);
        float4 kv[4], vv[4];
        #pragma unroll
        for (int j = 0; j < 4; j++) kv[j] = __ldcs(&K4[src_base + j * 256 + tid]);
        #pragma unroll
        for (int j = 0; j < 4; j++) vv[j] = __ldcs(&V4[src_base + j * 256 + tid]);
        #pragma unroll
        for (int j = 0; j < 4; j++) {
            int i = blk_base + j * 256 + tid;
            __stcs(&out4[K0_OFF / 4 + i], kv[j]);
            __stcs(&out4[V0_OFF / 4 + i], vv[j]);
        }
        return;
    }

    // ---- Pooling blocks -------------------------------------------------
    extern __shared__ float sm[];
    float* Ks  = sm;                 // 64*256
    float* q0s = Ks + 64 * C_;       // 256
    float* wsh = q0s + C_;           // 64
    float* red = wsh + 64;           // 32

    const int lane = tid & 31;
    const int wid  = tid >> 5;

    const int pb = blockIdx.x - NCOPYBLK;     // 0 .. NBLK1-1
    const int b = pb / NCHUNK_;
    const int n = pb % NCHUNK_;
    const size_t base = ((size_t)b * T_ + (size_t)n * STRIDE_) * C_;

    // Stage K chunk into smem (float4, evict-first: single DRAM touch)
    {
        const float4* Kg  = reinterpret_cast<const float4*>(K + base);
        float4*       Ks4 = reinterpret_cast<float4*>(Ks);
        #pragma unroll
        for (int i = 0; i < 16; i++)
            Ks4[i * 256 + tid] = __ldcs(&Kg[i * 256 + tid]);
        q0s[tid] = q0[tid];
    }
    __syncthreads();

    // Logits: warp wid handles rows s = wid*8 .. wid*8+7 (conflict-free LDS)
    {
        float qv[8];
        #pragma unroll
        for (int i = 0; i < 8; i++) qv[i] = q0s[lane + 32 * i];
        #pragma unroll
        for (int r = 0; r < 8; r++) {
            int s = wid * 8 + r;
            const float* row = Ks + s * C_;
            float acc = 0.f;
            #pragma unroll
            for (int i = 0; i < 8; i++) acc = fmaf(row[lane + 32 * i], qv[i], acc);
            #pragma unroll
            for (int off = 16; off; off >>= 1)
                acc += __shfl_xor_sync(0xffffffffu, acc, off);
            if (lane == 0) wsh[s] = acc;
        }
    }
    __syncthreads();

    // Softmax over 64 logits (warp 0), max-subtracted
    if (wid == 0) {
        float l0 = wsh[lane], l1 = wsh[lane + 32];
        float m = fmaxf(l0, l1);
        #pragma unroll
        for (int off = 16; off; off >>= 1)
            m = fmaxf(m, __shfl_xor_sync(0xffffffffu, m, off));
        float e0 = __expf(l0 - m), e1 = __expf(l1 - m);
        float ssum = e0 + e1;
        #pragma unroll
        for (int off = 16; off; off >>= 1)
            ssum += __shfl_xor_sync(0xffffffffu, ssum, off);
        float inv = 1.f / ssum;
        wsh[lane] = e0 * inv;
        wsh[lane + 32] = e1 * inv;
    }
    __syncthreads();

    // Per-column (thread = column c) merged pass:
    //   sk, sum(x), sum(x^2) from smem K; sv streamed from global V.
    const int c = tid;
    const float* Vg = V + base;
    float sk = 0.f, sx = 0.f, sxx = 0.f, sv = 0.f;
    #pragma unroll 8
    for (int s = 0; s < 64; s++) {
        float w = wsh[s];                    // broadcast LDS (free)
        float v = __ldcs(&Vg[s * C_ + c]);   // single-use stream, evict-first
        float x = Ks[s * C_ + c];
        sk  = fmaf(w, x, sk);
        sx += x;
        sxx = fmaf(x, x, sxx);
        sv  = fmaf(w, v, sv);
    }
    // sum_s (x - sk)^2 = sxx - 2*sk*sx + 64*sk^2
    float rp = sxx - 2.f * sk * sx + 64.f * sk * sk;

    // Outputs: only last W1_ chunks feed K1/V1
    if (n >= NCHUNK_ - W1_) {
        int j = n - (NCHUNK_ - W1_);
        size_t o = ((size_t)b * W1_ + j) * C_ + c;
        out[K1_OFF + o] = sk;
        out[V1_OFF + o] = sv;
    }

    // Block-reduce rp -> g_part1 (deterministic: fixed tree, fixed mapping)
    #pragma unroll
    for (int off = 16; off; off >>= 1)
        rp += __shfl_xor_sync(0xffffffffu, rp, off);
    if (lane == 0) red[wid] = rp;
    __syncthreads();
    if (wid == 0) {
        float v = (lane < 8) ? red[lane] : 0.f;
        #pragma unroll
        for (int off = 4; off; off >>= 1)
            v += __shfl_xor_sync(0xffffffffu, v, off);
        if (lane == 0)
            // rl[n] = sum/(B*stride*C); recon1 = sum_n rl[n] / NCHUNK
            g_part1[pb] = v * (1.0f / ((float)(B_ * STRIDE_ * C_) * (float)NCHUNK_));
    }
}

// ---------------------------------------------------------------------------
// Kernel 2: one WARP per pair; no block barriers in main path.
// Block = 256 thr = 8 warps = 8 pairs; grid = 64 blocks.
// The LAST block (counter election) does the deterministic recon reduction.
// ---------------------------------------------------------------------------
__global__ __launch_bounds__(256) void level2_kernel(
        const float* __restrict__ out_in, const float* __restrict__ q1,
        float* __restrict__ out) {
    __shared__ unsigned int s_last;
    __shared__ float redf[8];

    const int tid  = threadIdx.x;
    const int lane = tid & 31;
    const int wid  = tid >> 5;
    const int gp = blockIdx.x * 8 + wid;      // global pair 0..511
    const int b = gp >> 5;
    const int p = gp & 31;

    const float4* K1 = reinterpret_cast<const float4*>(out_in + K1_OFF);
    const float4* V1 = reinterpret_cast<const float4*>(out_in + V1_OFF);
    const float4* q4 = reinterpret_cast<const float4*>(q1);
    const int C4 = C_ / 4;                    // 64 float4 per row

    const size_t r0 = ((size_t)b * W1_ + 2 * p) * C4;   // float4 units
    float4 k0a = K1[r0 + lane],       k0b = K1[r0 + 32 + lane];
    float4 k1a = K1[r0 + C4 + lane],  k1b = K1[r0 + C4 + 32 + lane];
    float4 v0a = V1[r0 + lane],       v0b = V1[r0 + 32 + lane];
    float4 v1a = V1[r0 + C4 + lane],  v1b = V1[r0 + C4 + 32 + lane];
    float4 qa  = q4[lane],            qb  = q4[32 + lane];

    // Logits via pure warp shuffles (no smem, no barrier)
    float d0 = dot4(k0a, qa) + dot4(k0b, qb);
    float d1 = dot4(k1a, qa) + dot4(k1b, qb);
    #pragma unroll
    for (int off = 16; off; off >>= 1) {
        d0 += __shfl_xor_sync(0xffffffffu, d0, off);
        d1 += __shfl_xor_sync(0xffffffffu, d1, off);
    }
    float m = fmaxf(d0, d1);
    float e0 = __expf(d0 - m), e1 = __expf(d1 - m);
    float inv = 1.f / (e0 + e1);
    float w0 = e0 * inv, w1 = e1 * inv;

    float4 ska, skb, sva, svb;
    ska.x = w0*k0a.x + w1*k1a.x; ska.y = w0*k0a.y + w1*k1a.y;
    ska.z = w0*k0a.z + w1*k1a.z; ska.w = w0*k0a.w + w1*k1a.w;
    skb.x = w0*k0b.x + w1*k1b.x; skb.y = w0*k0b.y + w1*k1b.y;
    skb.z = w0*k0b.z + w1*k1b.z; skb.w = w0*k0b.w + w1*k1b.w;
    sva.x = w0*v0a.x + w1*v1a.x; sva.y = w0*v0a.y + w1*v1a.y;
    sva.z = w0*v0a.z + w1*v1a.z; sva.w = w0*v0a.w + w1*v1a.w;
    svb.x = w0*v0b.x + w1*v1b.x; svb.y = w0*v0b.y + w1*v1b.y;
    svb.z = w0*v0b.z + w1*v1b.z; svb.w = w0*v0b.w + w1*v1b.w;

    // Outputs: last W2_ pairs
    if (p >= 32 - W2_) {
        int j = p - (32 - W2_);
        size_t o = ((size_t)b * W2_ + j) * C4;
        float4* out4 = reinterpret_cast<float4*>(out);
        out4[K2_OFF / 4 + o + lane]      = ska;
        out4[K2_OFF / 4 + o + 32 + lane] = skb;
        out4[V2_OFF / 4 + o + lane]      = sva;
        out4[V2_OFF / 4 + o + 32 + lane] = svb;
    }

    // rl2 partial: sum over this pair's 2*C elements of (k - sk)^2
    float rp = 0.f;
    {
        float t;
        t = k0a.x-ska.x; rp = fmaf(t,t,rp);  t = k1a.x-ska.x; rp = fmaf(t,t,rp);
        t = k0a.y-ska.y; rp = fmaf(t,t,rp);  t = k1a.y-ska.y; rp = fmaf(t,t,rp);
        t = k0a.z-ska.z; rp = fmaf(t,t,rp);  t = k1a.z-ska.z; rp = fmaf(t,t,rp);
        t = k0a.w-ska.w; rp = fmaf(t,t,rp);  t = k1a.w-ska.w; rp = fmaf(t,t,rp);
        t = k0b.x-skb.x; rp = fmaf(t,t,rp);  t = k1b.x-skb.x; rp = fmaf(t,t,rp);
        t = k0b.y-skb.y; rp = fmaf(t,t,rp);  t = k1b.y-skb.y; rp = fmaf(t,t,rp);
        t = k0b.z-skb.z; rp = fmaf(t,t,rp);  t = k1b.z-skb.z; rp = fmaf(t,t,rp);
        t = k0b.w-skb.w; rp = fmaf(t,t,rp);  t = k1b.w-skb.w; rp = fmaf(t,t,rp);
    }
    #pragma unroll
    for (int off = 16; off; off >>= 1)
        rp += __shfl_xor_sync(0xffffffffu, rp, off);
    if (lane == 0)
        // rl2[p] = sum/(B*2*C); recon2 = 0.5 * sum_p rl2[p]
        g_part2[gp] = 0.5f * rp * (1.0f / (float)(B_ * 2 * C_));

    // ---- Last-block-done recon reduction --------------------------------
    __syncthreads();                           // all 8 warps' partials written
    if (tid == 0) {
        __threadfence();                       // make g_part2 writes visible
        unsigned int t = atomicAdd(&g_done2, 1u);
        s_last = (t == NBLK2 - 1) ? 1u : 0u;
    }
    __syncthreads();
    if (s_last) {
        __threadfence();                       // acquire all blocks' partials
        float a = 0.f;
        // Fixed index order + fixed thread mapping => deterministic sum
        for (int i = tid; i < NBLK1; i += 256) a += g_part1[i];
        for (int i = tid; i < NPAIR; i += 256) a += g_part2[i];
        #pragma unroll
        for (int off = 16; off; off >>= 1)
            a += __shfl_xor_sync(0xffffffffu, a, off);
        if (lane == 0) redf[wid] = a;
        __syncthreads();
        if (tid == 0) {
            float v = 0.f;
            #pragma unroll
            for (int i = 0; i < 8; i++) v += redf[i];
            out[RECON_OFF] = v;
            g_done2 = 0;                       // reset for next graph replay
        }
    }
}

// ---------------------------------------------------------------------------
extern "C" void kernel_launch(void* const* d_in, const int* in_sizes, int n_in,
                              void* d_out, int out_size) {
    const float* K  = (const float*)d_in[0];
    const float* V  = (const float*)d_in[1];
    const float* q0 = (const float*)d_in[2];
    const float* q1 = (const float*)d_in[3];
    float* out = (float*)d_out;

    // smem for level1: (64*256 + 256 + 64 + 32) floats = 66,944 bytes
    const int smem1 = (64 * C_ + C_ + 64 + 32) * sizeof(float);
    cudaFuncSetAttribute(level1_kernel,
                         cudaFuncAttributeMaxDynamicSharedMemorySize, smem1);

    // K0/V0 copy (front blocks) + level-1 pooling in one grid
    level1_kernel<<<NCOPYBLK + NBLK1, 256, smem1>>>(K, V, q0, out);
    // Level 2: warp-per-pair + fused deterministic recon reduction
    level2_kernel<<<NBLK2, 256>>>(out, q1, out);
}